// round 1
// baseline (speedup 1.0000x reference)
#include <cuda_runtime.h>
#include <math.h>

// Problem constants (from reference_code)
#define B_      16
#define H_      16
#define D_      128
#define MAXS    2048
#define NSPLIT  8
#define CHUNK   (MAXS / NSPLIT)   // 256 positions per split
#define NWARP   8
#define NTHREAD 256

// Split-KV partial scratch (allocation-free: __device__ globals)
__device__ float g_po[B_ * H_ * NSPLIT * D_];   // partial outputs (unnormalized)
__device__ float g_pm[B_ * H_ * NSPLIT];        // partial running max
__device__ float g_pl[B_ * H_ * NSPLIT];        // partial exp-sum

__global__ __launch_bounds__(NTHREAD) void paged_attn_split(
    const float* __restrict__ Q,            // [B,H,D]
    const float* __restrict__ K,            // [B,H,D]
    const float* __restrict__ V,            // [B,H,D]
    const float* __restrict__ Kc,           // [NUM_BLOCKS,16,H,D] = [flat_slot,H,D]
    const float* __restrict__ Vc,
    const float* __restrict__ cosT,         // [MAXS,1,D]
    const float* __restrict__ sinT,
    const float* __restrict__ mask,         // [B,MAXS]
    const int*   __restrict__ cache_length, // [B]
    const int*   __restrict__ fetch_slots)  // [B,128]
{
    const int split = blockIdx.x;
    const int h     = blockIdx.y;
    const int b     = blockIdx.z;
    const int tid   = threadIdx.x;
    const int w     = tid >> 5;
    const int lane  = tid & 31;

    const int newpos = cache_length[b];
    const int L      = newpos + 1;              // valid positions: s <= cache_length
    const int s0     = split * CHUNK;
    const int pidx   = (b * H_ + h) * NSPLIT + split;

    if (s0 >= L) {
        // inactive split: neutral partial
        if (tid < D_) g_po[pidx * D_ + tid] = 0.f;
        if (tid == 0) { g_pm[pidx] = -1e30f; g_pl[pidx] = 0.f; }
        return;
    }
    const int s1 = min(s0 + CHUNK, L);

    __shared__ float sh_q[D_];                  // RoPE'd Q row
    __shared__ float sh_k[D_];                  // RoPE'd new-token K row
    __shared__ float sh_v[D_];                  // new-token V row
    __shared__ float sh_m[NWARP];
    __shared__ float sh_l[NWARP];
    __shared__ float sh_acc[NWARP][D_];

    // RoPE on the new token (llama half-dim convention)
    if (tid < D_) {
        const float c  = cosT[(size_t)newpos * D_ + tid];
        const float sn = sinT[(size_t)newpos * D_ + tid];
        const float* qrow = Q + ((size_t)b * H_ + h) * D_;
        const float* krow = K + ((size_t)b * H_ + h) * D_;
        const float qrot = (tid < 64) ? -qrow[tid + 64] : qrow[tid - 64];
        const float krot = (tid < 64) ? -krow[tid + 64] : krow[tid - 64];
        sh_q[tid] = qrow[tid] * c + qrot * sn;
        sh_k[tid] = krow[tid] * c + krot * sn;
        sh_v[tid] = V[((size_t)b * H_ + h) * D_ + tid];
    }
    __syncthreads();

    const float4 q4 = reinterpret_cast<const float4*>(sh_q)[lane];
    const float scale = 0.08838834764831845f;   // 1/sqrt(128)

    float  m = -1e30f, l = 0.f;
    float4 acc = make_float4(0.f, 0.f, 0.f, 0.f);

    const int*   fs   = fetch_slots + b * 128;
    const float* mrow = mask + (size_t)b * MAXS;

    // Hot loop: cached positions only (strictly below newpos) — branch-free.
    const int s_cache_end = min(s1, newpos);
    for (int s = s0 + w; s < s_cache_end; s += NWARP) {
        const size_t slot = (size_t)fs[s >> 4] * 16 + (s & 15);
        const float4 k4 = reinterpret_cast<const float4*>(Kc + (slot * H_ + h) * D_)[lane];
        const float4 v4 = reinterpret_cast<const float4*>(Vc + (slot * H_ + h) * D_)[lane];

        float dot = q4.x * k4.x + q4.y * k4.y + q4.z * k4.z + q4.w * k4.w;
        #pragma unroll
        for (int o = 16; o; o >>= 1) dot += __shfl_xor_sync(0xffffffffu, dot, o);

        const float score = dot * scale + mrow[s];
        const float mn   = fmaxf(m, score);
        const float corr = __expf(m - mn);
        const float p    = __expf(score - mn);
        l = l * corr + p;
        acc.x = acc.x * corr + p * v4.x;
        acc.y = acc.y * corr + p * v4.y;
        acc.z = acc.z * corr + p * v4.z;
        acc.w = acc.w * corr + p * v4.w;
        m = mn;
    }

    // New token (position == cache_length[b]) handled once, by warp 0 of the
    // split that owns it. Uses RoPE'd K and input V from shared.
    if (w == 0 && newpos >= s0 && newpos < s1) {
        const float4 k4 = reinterpret_cast<const float4*>(sh_k)[lane];
        const float4 v4 = reinterpret_cast<const float4*>(sh_v)[lane];
        float dot = q4.x * k4.x + q4.y * k4.y + q4.z * k4.z + q4.w * k4.w;
        #pragma unroll
        for (int o = 16; o; o >>= 1) dot += __shfl_xor_sync(0xffffffffu, dot, o);
        const float score = dot * scale + mrow[newpos];
        const float mn   = fmaxf(m, score);
        const float corr = __expf(m - mn);
        const float p    = __expf(score - mn);
        l = l * corr + p;
        acc.x = acc.x * corr + p * v4.x;
        acc.y = acc.y * corr + p * v4.y;
        acc.z = acc.z * corr + p * v4.z;
        acc.w = acc.w * corr + p * v4.w;
        m = mn;
    }

    // Merge the 8 warps' partial softmax states in shared memory.
    if (lane == 0) { sh_m[w] = m; sh_l[w] = l; }
    reinterpret_cast<float4*>(sh_acc[w])[lane] = acc;
    __syncthreads();

    if (tid < D_) {
        float M = sh_m[0];
        #pragma unroll
        for (int i = 1; i < NWARP; i++) M = fmaxf(M, sh_m[i]);
        float od = 0.f, lt = 0.f;
        #pragma unroll
        for (int i = 0; i < NWARP; i++) {
            const float e = __expf(sh_m[i] - M);
            od += e * sh_acc[i][tid];
            lt += e * sh_l[i];
        }
        g_po[pidx * D_ + tid] = od;
        if (tid == 0) { g_pm[pidx] = M; g_pl[pidx] = lt; }
    }
}

__global__ __launch_bounds__(D_) void paged_attn_combine(float* __restrict__ out)
{
    const int bh = blockIdx.x;      // b*H + h
    const int d  = threadIdx.x;     // 0..127

    float M = -1e30f;
    #pragma unroll
    for (int i = 0; i < NSPLIT; i++) M = fmaxf(M, g_pm[bh * NSPLIT + i]);

    float denom = 0.f, od = 0.f;
    #pragma unroll
    for (int i = 0; i < NSPLIT; i++) {
        const float e = __expf(g_pm[bh * NSPLIT + i] - M);
        denom += e * g_pl[bh * NSPLIT + i];
        od    += e * g_po[(bh * NSPLIT + i) * D_ + d];
    }
    out[bh * D_ + d] = od / denom;
}

// Inputs (metadata order, from setup_inputs dict):
//  0 Q [B,H,D] f32          1 K [B,H,D] f32        2 V [B,H,D] f32
//  3 Kcache f32             4 Vcache f32
//  5 cos [MAXS,1,D] f32     6 sin [MAXS,1,D] f32   7 mask [B,MAXS] f32
//  8 input_length i32       9 cache_length i32    10 save_slots i32
// 11 fetch_slots [B,128] i32                      12 max_s (scalar)
extern "C" void kernel_launch(void* const* d_in, const int* in_sizes, int n_in,
                              void* d_out, int out_size)
{
    const float* Q    = (const float*)d_in[0];
    const float* K    = (const float*)d_in[1];
    const float* V    = (const float*)d_in[2];
    const float* Kc   = (const float*)d_in[3];
    const float* Vc   = (const float*)d_in[4];
    const float* cosT = (const float*)d_in[5];
    const float* sinT = (const float*)d_in[6];
    const float* mask = (const float*)d_in[7];
    const int*   clen = (const int*)d_in[9];
    const int*   fsl  = (const int*)d_in[11];
    float* out = (float*)d_out;

    dim3 grid(NSPLIT, H_, B_);
    paged_attn_split<<<grid, NTHREAD>>>(Q, K, V, Kc, Vc, cosT, sinT, mask, clen, fsl);
    paged_attn_combine<<<B_ * H_, D_>>>(out);
}

// round 2
// speedup vs baseline: 1.0339x; 1.0339x over previous
#include <cuda_runtime.h>
#include <math.h>

// Problem constants (from reference_code)
#define B_      16
#define H_      16
#define D_      128
#define MAXS    2048
#define NSPLIT  8
#define CHUNK   (MAXS / NSPLIT)   // 256 positions per split
#define NWARP   8
#define NTHREAD 256

// Split-KV partial scratch (allocation-free: __device__ globals)
__device__ float g_po[B_ * H_ * NSPLIT * D_];   // partial outputs (unnormalized)
__device__ float g_pm[B_ * H_ * NSPLIT];        // partial running max
__device__ float g_pl[B_ * H_ * NSPLIT];        // partial exp-sum
__device__ unsigned int g_cnt[B_ * H_];         // arrival counters (zero-init; reset by last CTA)

__device__ __forceinline__ void online_update(
    float& m, float& l, float4& acc, float score, const float4& v4)
{
    const float mn   = fmaxf(m, score);
    const float corr = __expf(m - mn);
    const float p    = __expf(score - mn);
    l = l * corr + p;
    acc.x = acc.x * corr + p * v4.x;
    acc.y = acc.y * corr + p * v4.y;
    acc.z = acc.z * corr + p * v4.z;
    acc.w = acc.w * corr + p * v4.w;
    m = mn;
}

__global__ __launch_bounds__(NTHREAD) void paged_attn_fused(
    const float* __restrict__ Q,            // [B,H,D]
    const float* __restrict__ K,            // [B,H,D]
    const float* __restrict__ V,            // [B,H,D]
    const float* __restrict__ Kc,           // [flat_slot,H,D]
    const float* __restrict__ Vc,
    const float* __restrict__ cosT,         // [MAXS,1,D]
    const float* __restrict__ sinT,
    const float* __restrict__ mask,         // [B,MAXS]
    const int*   __restrict__ cache_length, // [B]
    const int*   __restrict__ fetch_slots,  // [B,128]
    float*       __restrict__ out)          // [B,H,D]
{
    const int split = blockIdx.x;
    const int h     = blockIdx.y;
    const int b     = blockIdx.z;
    const int tid   = threadIdx.x;
    const int w     = tid >> 5;
    const int lane  = tid & 31;

    const int newpos = cache_length[b];
    const int L      = newpos + 1;              // valid positions: s <= cache_length
    const int s0     = split * CHUNK;
    const int bh     = b * H_ + h;
    const int pbase  = bh * NSPLIT;
    const int nact   = min(NSPLIT, (L + CHUNK - 1) / CHUNK);  // # active splits

    __shared__ float sh_q[D_];
    __shared__ float sh_k[D_];
    __shared__ float sh_v[D_];
    __shared__ float sh_m[NWARP];
    __shared__ float sh_l[NWARP];
    __shared__ float sh_acc[NWARP][D_];
    __shared__ unsigned int sh_rank;

    const bool active = (s0 < L);

    if (active) {
        const int s1 = min(s0 + CHUNK, L);

        // RoPE on the new token (llama half-dim convention)
        if (tid < D_) {
            const float c  = cosT[(size_t)newpos * D_ + tid];
            const float sn = sinT[(size_t)newpos * D_ + tid];
            const float* qrow = Q + ((size_t)bh) * D_;
            const float* krow = K + ((size_t)bh) * D_;
            const float qrot = (tid < 64) ? -qrow[tid + 64] : qrow[tid - 64];
            const float krot = (tid < 64) ? -krow[tid + 64] : krow[tid - 64];
            sh_q[tid] = qrow[tid] * c + qrot * sn;
            sh_k[tid] = krow[tid] * c + krot * sn;
            sh_v[tid] = V[((size_t)bh) * D_ + tid];
        }
        __syncthreads();

        const float4 q4 = reinterpret_cast<const float4*>(sh_q)[lane];
        const float scale = 0.08838834764831845f;   // 1/sqrt(128)

        float  m = -1e30f, l = 0.f;
        float4 acc = make_float4(0.f, 0.f, 0.f, 0.f);

        const int*   fs   = fetch_slots + b * 128;
        const float* mrow = mask + (size_t)b * MAXS;

        // Hot loop over cached positions (strictly below newpos), 2x unrolled:
        // each warp covers s and s+8 per iteration -> 4 in-flight LDG.128.
        const int send = min(s1, newpos);
        int s = s0 + w;
        for (; s + NWARP < send; s += 2 * NWARP) {
            const int sA = s, sB = s + NWARP;
            const size_t slotA = (size_t)fs[sA >> 4] * 16 + (sA & 15);
            const size_t slotB = (size_t)fs[sB >> 4] * 16 + (sB & 15);
            const float4 k4a = reinterpret_cast<const float4*>(Kc + (slotA * H_ + h) * D_)[lane];
            const float4 v4a = reinterpret_cast<const float4*>(Vc + (slotA * H_ + h) * D_)[lane];
            const float4 k4b = reinterpret_cast<const float4*>(Kc + (slotB * H_ + h) * D_)[lane];
            const float4 v4b = reinterpret_cast<const float4*>(Vc + (slotB * H_ + h) * D_)[lane];

            float dotA = q4.x * k4a.x + q4.y * k4a.y + q4.z * k4a.z + q4.w * k4a.w;
            float dotB = q4.x * k4b.x + q4.y * k4b.y + q4.z * k4b.z + q4.w * k4b.w;
            #pragma unroll
            for (int o = 16; o; o >>= 1) {
                dotA += __shfl_xor_sync(0xffffffffu, dotA, o);
                dotB += __shfl_xor_sync(0xffffffffu, dotB, o);
            }
            online_update(m, l, acc, dotA * scale + mrow[sA], v4a);
            online_update(m, l, acc, dotB * scale + mrow[sB], v4b);
        }
        if (s < send) {
            const size_t slot = (size_t)fs[s >> 4] * 16 + (s & 15);
            const float4 k4 = reinterpret_cast<const float4*>(Kc + (slot * H_ + h) * D_)[lane];
            const float4 v4 = reinterpret_cast<const float4*>(Vc + (slot * H_ + h) * D_)[lane];
            float dot = q4.x * k4.x + q4.y * k4.y + q4.z * k4.z + q4.w * k4.w;
            #pragma unroll
            for (int o = 16; o; o >>= 1) dot += __shfl_xor_sync(0xffffffffu, dot, o);
            online_update(m, l, acc, dot * scale + mrow[s], v4);
        }

        // New token (position == cache_length[b]) once, warp 0 of owning split.
        if (w == 0 && newpos >= s0 && newpos < s1) {
            const float4 k4 = reinterpret_cast<const float4*>(sh_k)[lane];
            const float4 v4 = reinterpret_cast<const float4*>(sh_v)[lane];
            float dot = q4.x * k4.x + q4.y * k4.y + q4.z * k4.z + q4.w * k4.w;
            #pragma unroll
            for (int o = 16; o; o >>= 1) dot += __shfl_xor_sync(0xffffffffu, dot, o);
            online_update(m, l, acc, dot * scale + mrow[newpos], v4);
        }

        // Merge the 8 warps in shared memory, write this split's partial.
        if (lane == 0) { sh_m[w] = m; sh_l[w] = l; }
        reinterpret_cast<float4*>(sh_acc[w])[lane] = acc;
        __syncthreads();

        if (tid < D_) {
            float M = sh_m[0];
            #pragma unroll
            for (int i = 1; i < NWARP; i++) M = fmaxf(M, sh_m[i]);
            float od = 0.f, lt = 0.f;
            #pragma unroll
            for (int i = 0; i < NWARP; i++) {
                const float e = __expf(sh_m[i] - M);
                od += e * sh_acc[i][tid];
                lt += e * sh_l[i];
            }
            g_po[(pbase + split) * D_ + tid] = od;
            if (tid == 0) { g_pm[pbase + split] = M; g_pl[pbase + split] = lt; }
        }
        __threadfence();   // make partials visible before arrival
    }

    // Arrival + last-CTA combine (all NSPLIT CTAs of this (b,h) participate).
    if (tid == 0) sh_rank = atomicAdd(&g_cnt[bh], 1u);
    __syncthreads();

    if (sh_rank == NSPLIT - 1) {
        if (tid < D_) {
            float M = -1e30f;
            for (int i = 0; i < nact; i++) M = fmaxf(M, g_pm[pbase + i]);
            float denom = 0.f, od = 0.f;
            for (int i = 0; i < nact; i++) {
                const float e = __expf(g_pm[pbase + i] - M);
                denom += e * g_pl[pbase + i];
                od    += e * g_po[(pbase + i) * D_ + tid];
            }
            out[(size_t)bh * D_ + tid] = od / denom;
        }
        if (tid == 0) g_cnt[bh] = 0;   // reset for next graph replay (deterministic)
    }
}

// Inputs (metadata order):
//  0 Q  1 K  2 V  3 Kcache  4 Vcache  5 cos  6 sin  7 mask
//  8 input_length  9 cache_length  10 save_slots  11 fetch_slots  12 max_s
extern "C" void kernel_launch(void* const* d_in, const int* in_sizes, int n_in,
                              void* d_out, int out_size)
{
    const float* Q    = (const float*)d_in[0];
    const float* K    = (const float*)d_in[1];
    const float* V    = (const float*)d_in[2];
    const float* Kc   = (const float*)d_in[3];
    const float* Vc   = (const float*)d_in[4];
    const float* cosT = (const float*)d_in[5];
    const float* sinT = (const float*)d_in[6];
    const float* mask = (const float*)d_in[7];
    const int*   clen = (const int*)d_in[9];
    const int*   fsl  = (const int*)d_in[11];
    float* out = (float*)d_out;

    dim3 grid(NSPLIT, H_, B_);
    paged_attn_fused<<<grid, NTHREAD>>>(Q, K, V, Kc, Vc, cosT, sinT, mask, clen, fsl, out);
}

// round 4
// speedup vs baseline: 1.0659x; 1.0310x over previous
#include <cuda_runtime.h>
#include <math.h>

#define B_      16
#define H_      16
#define D_      128
#define MAXS    2048
#define NSPLIT  8
#define NWARP   8
#define NTHREAD 256
#define CHUNKMAX 256    // ceil(2047/8) = 256

// Split-KV partial scratch (allocation-free: __device__ globals)
__device__ float g_po[B_ * H_ * NSPLIT * D_];
__device__ float g_pm[B_ * H_ * NSPLIT];
__device__ float g_pl[B_ * H_ * NSPLIT];
__device__ unsigned int g_cnt[B_ * H_];   // zero-init; reset by last CTA each call

__global__ __launch_bounds__(NTHREAD) void paged_attn_fused(
    const float* __restrict__ Q,
    const float* __restrict__ K,
    const float* __restrict__ V,
    const float* __restrict__ Kc,           // [flat_slot,H,D]
    const float* __restrict__ Vc,
    const float* __restrict__ cosT,         // [MAXS,1,D]
    const float* __restrict__ sinT,
    const float* __restrict__ mask,         // [B,MAXS]
    const int*   __restrict__ cache_length, // [B]
    const int*   __restrict__ fetch_slots,  // [B,128]
    float*       __restrict__ out)          // [B,H,D]
{
    const int split = blockIdx.x;
    const int h     = blockIdx.y;
    const int b     = blockIdx.z;
    const int tid   = threadIdx.x;
    const int w     = tid >> 5;
    const int lane  = tid & 31;

    const int newpos = cache_length[b];
    const int L      = newpos + 1;
    const int bh     = b * H_ + h;
    const int pbase  = bh * NSPLIT;

    // Dynamic per-batch chunking: all 8 splits carry (nearly) equal length.
    const int chunk = (L + NSPLIT - 1) / NSPLIT;
    const int s0    = split * chunk;
    const int nact  = min(NSPLIT, (L + chunk - 1) / chunk);

    // All float4-accessed shared arrays explicitly 16B-aligned; oddly sized
    // arrays (sh_fs, scalars) placed after them.
    __shared__ __align__(16) float sh_q[D_];
    __shared__ __align__(16) float sh_k[D_];
    __shared__ __align__(16) float sh_v[D_];
    __shared__ __align__(16) float sh_acc[NWARP][D_];
    __shared__ __align__(16) float sh_mask[CHUNKMAX];
    __shared__ float sh_m[NWARP];
    __shared__ float sh_l[NWARP];
    __shared__ int   sh_fs[CHUNKMAX / 16 + 2];
    __shared__ unsigned int sh_rank;

    const bool active = (s0 < L);

    if (active) {
        const int s1  = min(s0 + chunk, L);
        const int len = s1 - s0;
        const int f0  = s0 >> 4;                       // first block-table entry
        const int nfs = ((s1 - 1) >> 4) - f0 + 1;      // #entries this chunk touches

        // Prologue: RoPE'd Q/K + new-token V, mask chunk, fetch-slot chunk.
        if (tid < D_) {
            const float c  = cosT[(size_t)newpos * D_ + tid];
            const float sn = sinT[(size_t)newpos * D_ + tid];
            const float* qrow = Q + (size_t)bh * D_;
            const float* krow = K + (size_t)bh * D_;
            const float qrot = (tid < 64) ? -qrow[tid + 64] : qrow[tid - 64];
            const float krot = (tid < 64) ? -krow[tid + 64] : krow[tid - 64];
            sh_q[tid] = qrow[tid] * c + qrot * sn;
            sh_k[tid] = krow[tid] * c + krot * sn;
            sh_v[tid] = V[(size_t)bh * D_ + tid];
        }
        for (int i = tid; i < len; i += NTHREAD)
            sh_mask[i] = mask[(size_t)b * MAXS + s0 + i];
        if (tid < nfs)
            sh_fs[tid] = fetch_slots[b * 128 + f0 + tid];
        __syncthreads();

        const float4 q4 = reinterpret_cast<const float4*>(sh_q)[lane];
        const float scale = 0.08838834764831845f;   // 1/sqrt(128)

        float  m = -1e30f, l = 0.f;
        float4 acc = make_float4(0.f, 0.f, 0.f, 0.f);

        // Hot loop: cached positions strictly below newpos, 2-way unrolled with
        // a fused 2-element online-softmax update (1 corr exp instead of 2).
        const int send = min(s1, newpos);
        int s = s0 + w;
        for (; s + NWARP < send; s += 2 * NWARP) {
            const int sA = s, sB = s + NWARP;
            const int slotA = sh_fs[(sA >> 4) - f0] * 16 + (sA & 15);
            const int slotB = sh_fs[(sB >> 4) - f0] * 16 + (sB & 15);
            const float4 k4a = __ldcs(reinterpret_cast<const float4*>(Kc + ((size_t)slotA * H_ + h) * D_) + lane);
            const float4 v4a = __ldcs(reinterpret_cast<const float4*>(Vc + ((size_t)slotA * H_ + h) * D_) + lane);
            const float4 k4b = __ldcs(reinterpret_cast<const float4*>(Kc + ((size_t)slotB * H_ + h) * D_) + lane);
            const float4 v4b = __ldcs(reinterpret_cast<const float4*>(Vc + ((size_t)slotB * H_ + h) * D_) + lane);

            float dotA = q4.x * k4a.x + q4.y * k4a.y + q4.z * k4a.z + q4.w * k4a.w;
            float dotB = q4.x * k4b.x + q4.y * k4b.y + q4.z * k4b.z + q4.w * k4b.w;
            #pragma unroll
            for (int o = 16; o; o >>= 1) {
                dotA += __shfl_xor_sync(0xffffffffu, dotA, o);
                dotB += __shfl_xor_sync(0xffffffffu, dotB, o);
            }
            const float scA = dotA * scale + sh_mask[sA - s0];
            const float scB = dotB * scale + sh_mask[sB - s0];

            const float mn   = fmaxf(m, fmaxf(scA, scB));
            const float corr = __expf(m - mn);
            const float pA   = __expf(scA - mn);
            const float pB   = __expf(scB - mn);
            l = l * corr + pA + pB;
            acc.x = acc.x * corr + pA * v4a.x + pB * v4b.x;
            acc.y = acc.y * corr + pA * v4a.y + pB * v4b.y;
            acc.z = acc.z * corr + pA * v4a.z + pB * v4b.z;
            acc.w = acc.w * corr + pA * v4a.w + pB * v4b.w;
            m = mn;
        }
        if (s < send) {
            const int slot = sh_fs[(s >> 4) - f0] * 16 + (s & 15);
            const float4 k4 = __ldcs(reinterpret_cast<const float4*>(Kc + ((size_t)slot * H_ + h) * D_) + lane);
            const float4 v4 = __ldcs(reinterpret_cast<const float4*>(Vc + ((size_t)slot * H_ + h) * D_) + lane);
            float dot = q4.x * k4.x + q4.y * k4.y + q4.z * k4.z + q4.w * k4.w;
            #pragma unroll
            for (int o = 16; o; o >>= 1) dot += __shfl_xor_sync(0xffffffffu, dot, o);
            const float sc = dot * scale + sh_mask[s - s0];
            const float mn   = fmaxf(m, sc);
            const float corr = __expf(m - mn);
            const float p    = __expf(sc - mn);
            l = l * corr + p;
            acc.x = acc.x * corr + p * v4.x;
            acc.y = acc.y * corr + p * v4.y;
            acc.z = acc.z * corr + p * v4.z;
            acc.w = acc.w * corr + p * v4.w;
            m = mn;
        }

        // New token (position == cache_length[b]): warp 0 of the owning split.
        if (w == 0 && newpos >= s0 && newpos < s1) {
            const float4 k4 = reinterpret_cast<const float4*>(sh_k)[lane];
            const float4 v4 = reinterpret_cast<const float4*>(sh_v)[lane];
            float dot = q4.x * k4.x + q4.y * k4.y + q4.z * k4.z + q4.w * k4.w;
            #pragma unroll
            for (int o = 16; o; o >>= 1) dot += __shfl_xor_sync(0xffffffffu, dot, o);
            const float sc = dot * scale + sh_mask[newpos - s0];
            const float mn   = fmaxf(m, sc);
            const float corr = __expf(m - mn);
            const float p    = __expf(sc - mn);
            l = l * corr + p;
            acc.x = acc.x * corr + p * v4.x;
            acc.y = acc.y * corr + p * v4.y;
            acc.z = acc.z * corr + p * v4.z;
            acc.w = acc.w * corr + p * v4.w;
            m = mn;
        }

        // Merge 8 warps in shared, write this split's partial.
        if (lane == 0) { sh_m[w] = m; sh_l[w] = l; }
        reinterpret_cast<float4*>(sh_acc[w])[lane] = acc;
        __syncthreads();

        if (tid < D_) {
            float M = sh_m[0];
            #pragma unroll
            for (int i = 1; i < NWARP; i++) M = fmaxf(M, sh_m[i]);
            float od = 0.f, lt = 0.f;
            #pragma unroll
            for (int i = 0; i < NWARP; i++) {
                const float e = __expf(sh_m[i] - M);
                od += e * sh_acc[i][tid];
                lt += e * sh_l[i];
            }
            g_po[(pbase + split) * D_ + tid] = od;
            if (tid == 0) { g_pm[pbase + split] = M; g_pl[pbase + split] = lt; }
        }
        __threadfence();
    }

    // Arrival + last-CTA combine.
    if (tid == 0) sh_rank = atomicAdd(&g_cnt[bh], 1u);
    __syncthreads();

    if (sh_rank == NSPLIT - 1) {
        if (tid < D_) {
            float M = -1e30f;
            for (int i = 0; i < nact; i++) M = fmaxf(M, g_pm[pbase + i]);
            float denom = 0.f, od = 0.f;
            for (int i = 0; i < nact; i++) {
                const float e = __expf(g_pm[pbase + i] - M);
                denom += e * g_pl[pbase + i];
                od    += e * g_po[(pbase + i) * D_ + tid];
            }
            out[(size_t)bh * D_ + tid] = od / denom;
        }
        if (tid == 0) g_cnt[bh] = 0;   // reset for next graph replay
    }
}

// Inputs (metadata order):
//  0 Q  1 K  2 V  3 Kcache  4 Vcache  5 cos  6 sin  7 mask
//  8 input_length  9 cache_length  10 save_slots  11 fetch_slots  12 max_s
extern "C" void kernel_launch(void* const* d_in, const int* in_sizes, int n_in,
                              void* d_out, int out_size)
{
    const float* Q    = (const float*)d_in[0];
    const float* K    = (const float*)d_in[1];
    const float* V    = (const float*)d_in[2];
    const float* Kc   = (const float*)d_in[3];
    const float* Vc   = (const float*)d_in[4];
    const float* cosT = (const float*)d_in[5];
    const float* sinT = (const float*)d_in[6];
    const float* mask = (const float*)d_in[7];
    const int*   clen = (const int*)d_in[9];
    const int*   fsl  = (const int*)d_in[11];
    float* out = (float*)d_out;

    dim3 grid(NSPLIT, H_, B_);
    paged_attn_fused<<<grid, NTHREAD>>>(Q, K, V, Kc, Vc, cosT, sinT, mask, clen, fsl, out);
}